// round 12
// baseline (speedup 1.0000x reference)
#include <cuda_runtime.h>
#include <cuda_bf16.h>
#include <cstdint>
#include <math.h>

// ---------------------------------------------------------------------------
// B=32, T=512, M=16384.  Layers (Fin,U): (512,1024)(1024,128)(128,23)
// (151,256)(256,128)(128,8).  Wavefront: step s, layer l does t = s - l.
// Phase-1 per tile: P[32b,128n] = H[32,K] @ W[K,128] via mma.sync bf16
// split precision (hi*hi + hi*lo + lo*hi), fp32 accumulators.
// ---------------------------------------------------------------------------
#define NSTEPS 517

__device__ __align__(256) float g_xp [16384ull * 3072];
__device__ __align__(256) float g_seq1[16384ull * 1024];
__device__ __align__(256) float g_cat [16384ull * 151];
__device__ __align__(256) float g_seq4[16384ull * 256];
__device__ __align__(256) float g_seq5[16384ull * 128];
__device__ __align__(256) float g_h   [50144];     // [b][U] per layer, concat
__device__ __align__(256) float g_P   [600000];    // partial slots
__device__ unsigned int g_cnt[8 * 32];             // 8 group counters, padded
__device__ unsigned int g_root;
__device__ unsigned int g_gen;

struct WParams {
    const float* Kw[6];
    const float* Rw[6];
    const float* Bw[6];
    float* out;
};

// smem layout (byte offsets). W rows padded to 136 bf16 (272 B ≡ 4 banks),
// H rows padded to 264 bf16 (528 B ≡ 4 banks) -> ldmatrix conflict-free.
#define OFF_WHI 0                    // 256 x 272 B = 69632
#define OFF_WLO 69632
#define OFF_HHI 139264               // 32 x 528 B = 16896
#define OFF_HLO 156160
#define WF_SMEM 173056
#define WSTR 272
#define HSTR 528

// ---------------- hierarchical grid barrier ----------------
__device__ __forceinline__ void grid_sync(int gper)
{
    __syncthreads();
    if (threadIdx.x == 0) {
        unsigned int gen;
        asm volatile("ld.relaxed.gpu.u32 %0, [%1];"
                     : "=r"(gen) : "l"(&g_gen) : "memory");
        unsigned int* cnt = &g_cnt[(blockIdx.x & 7) * 32];
        unsigned int prev;
        asm volatile("atom.acq_rel.gpu.add.u32 %0, [%1], %2;"
                     : "=r"(prev) : "l"(cnt), "r"(1u) : "memory");
        if (prev == (unsigned)gper - 1u) {
            unsigned int rprev;
            asm volatile("atom.acq_rel.gpu.add.u32 %0, [%1], %2;"
                         : "=r"(rprev) : "l"(&g_root), "r"(1u) : "memory");
            if (rprev == 7u) {
                unsigned int zero = 0;
#pragma unroll
                for (int g = 0; g < 8; g++)
                    asm volatile("st.relaxed.gpu.u32 [%0], %1;"
                                 :: "l"(&g_cnt[g * 32]), "r"(zero) : "memory");
                asm volatile("st.relaxed.gpu.u32 [%0], %1;"
                             :: "l"(&g_root), "r"(zero) : "memory");
                asm volatile("st.release.gpu.u32 [%0], %1;"
                             :: "l"(&g_gen), "r"(gen + 1u) : "memory");
            }
        }
        unsigned int cur;
        do {
            asm volatile("ld.acquire.gpu.u32 %0, [%1];"
                         : "=r"(cur) : "l"(&g_gen) : "memory");
        } while (cur == gen);
    }
    __syncthreads();
}

__device__ __forceinline__ float sigf(float x)
{
    return 1.f / (1.f + __expf(-x));
}

// ---------------- mma helpers ----------------
__device__ __forceinline__ uint32_t smem_u32(const void* p)
{
    uint32_t a;
    asm("{ .reg .u64 t; cvta.to.shared.u64 t, %1; cvt.u32.u64 %0, t; }"
        : "=r"(a) : "l"(p));
    return a;
}
__device__ __forceinline__ void ldsm4(uint32_t* r, uint32_t addr)
{
    asm volatile("ldmatrix.sync.aligned.m8n8.x4.shared.b16 {%0,%1,%2,%3}, [%4];"
                 : "=r"(r[0]), "=r"(r[1]), "=r"(r[2]), "=r"(r[3]) : "r"(addr));
}
__device__ __forceinline__ void ldsm4t(uint32_t* r, uint32_t addr)
{
    asm volatile("ldmatrix.sync.aligned.m8n8.x4.trans.shared.b16 {%0,%1,%2,%3}, [%4];"
                 : "=r"(r[0]), "=r"(r[1]), "=r"(r[2]), "=r"(r[3]) : "r"(addr));
}
__device__ __forceinline__ void mma16816(float* c, const uint32_t* a, const uint32_t* b)
{
    asm volatile(
        "mma.sync.aligned.m16n8k16.row.col.f32.bf16.bf16.f32 "
        "{%0,%1,%2,%3}, {%4,%5,%6,%7}, {%8,%9}, {%0,%1,%2,%3};"
        : "+f"(c[0]), "+f"(c[1]), "+f"(c[2]), "+f"(c[3])
        : "r"(a[0]), "r"(a[1]), "r"(a[2]), "r"(a[3]), "r"(b[0]), "r"(b[1]));
}

// ---------------------------------------------------------------------------
// GEMM for layer-0 input projections: C[16384,3072] = X[16384,512]@K1 + b
// ---------------------------------------------------------------------------
__global__ __launch_bounds__(256) void gemm_bias_kernel(
    const float* __restrict__ A, int lda,
    const float* __restrict__ W,
    const float* __restrict__ bias,
    float* __restrict__ C,
    int N, int K)
{
    __shared__ float As[128][20];
    __shared__ float Bs[16][64];

    const int tid = threadIdx.x;
    const int m0  = blockIdx.y * 128;
    const int n0  = blockIdx.x * 64;
    const int nx  = tid & 15;
    const int my  = tid >> 4;

    float acc[8][4];
#pragma unroll
    for (int i = 0; i < 8; i++)
#pragma unroll
        for (int j = 0; j < 4; j++) acc[i][j] = 0.f;

    for (int k0 = 0; k0 < K; k0 += 16) {
        __syncthreads();
#pragma unroll
        for (int e = 0; e < 2; e++) {
            int idx = tid * 2 + e;
            int row = idx >> 2;
            int kq4 = (idx & 3) * 4;
            float4 v = *(const float4*)&A[(size_t)(m0 + row) * lda + k0 + kq4];
            *(float4*)&As[row][kq4] = v;
        }
        {
            int r   = tid >> 4;
            int nq4 = (tid & 15) * 4;
            float4 v = *(const float4*)&W[(size_t)(k0 + r) * N + n0 + nq4];
            *(float4*)&Bs[r][nq4] = v;
        }
        __syncthreads();
#pragma unroll
        for (int kk = 0; kk < 16; kk++) {
            float bv[4];
            *(float4*)bv = *(const float4*)&Bs[kk][nx * 4];
            float av[8];
#pragma unroll
            for (int i = 0; i < 8; i++) av[i] = As[my * 8 + i][kk];
#pragma unroll
            for (int i = 0; i < 8; i++)
#pragma unroll
                for (int j = 0; j < 4; j++)
                    acc[i][j] = fmaf(av[i], bv[j], acc[i][j]);
        }
    }
#pragma unroll
    for (int i = 0; i < 8; i++) {
        int m = m0 + my * 8 + i;
#pragma unroll
        for (int j = 0; j < 4; j++) {
            int n = n0 + nx * 4 + j;
            C[(size_t)m * N + n] = acc[i][j] + bias[n];
        }
    }
}

// ---------------------------------------------------------------------------
// Phase-2 gate math, one output element, compile-time layer constants.
// ---------------------------------------------------------------------------
template<int L, int U, int TU, int IS, int NS, int PO, int HO, int RELU>
__device__ __forceinline__ void gate_one(int r, int s, const WParams& prm)
{
    int t = s - L;
    if ((unsigned)t >= 512u) return;
    int b = r / U;
    int u = r - b * U;
    size_t row = (size_t)b * 512 + t;

    const float* Bl = prm.Bw[L];
    float xz, xr, xh;
    if (L == 0) {
        const float* xrow = g_xp + row * 3072;
        xz = xrow[u]; xr = xrow[1024 + u]; xh = xrow[2048 + u];
    } else {
        xz = Bl[u]; xr = Bl[U + u]; xh = Bl[2 * U + u];
#pragma unroll
        for (int s2 = 0; s2 < IS; s2++) {
            const float* pp = g_P + PO + ((size_t)s2 * 32 + b) * TU;
            xz += __ldcg(pp + u);
            xr += __ldcg(pp + U + u);
            xh += __ldcg(pp + 2 * U + u);
        }
    }
    const float* Br = Bl + TU;
    float rz = Br[u], rr = Br[U + u], rh = Br[2 * U + u];
#pragma unroll
    for (int s2 = IS; s2 < NS; s2++) {
        const float* pp = g_P + PO + ((size_t)s2 * 32 + b) * TU;
        rz += __ldcg(pp + u);
        rr += __ldcg(pp + U + u);
        rh += __ldcg(pp + 2 * U + u);
    }
    float z  = sigf(xz + rz);
    float rg = sigf(xr + rr);
    float hh = xh + rg * rh;
    if (RELU) hh = fmaxf(hh, 0.f);
    float* hptr = g_h + HO + b * U + u;
    float hp = __ldcg(hptr);
    float hn = z * hp + (1.f - z) * hh;
    *hptr = hn;
    if (L == 0)      g_seq1[row * 1024 + u] = hn;
    else if (L == 1) g_cat[row * 151 + u] = hn;
    else if (L == 2) { g_cat[row * 151 + 128 + u] = hn;
                       prm.out[row * 23 + u] = hn; }
    else if (L == 3) g_seq4[row * 256 + u] = hn;
    else if (L == 4) g_seq5[row * 128 + u] = hn;
    else             prm.out[16384ull * 23 + row * 8 + u] = hn;
}

// ---------------------------------------------------------------------------
// Persistent wavefront kernel, HMMA (mma.sync) phase-1.
// ---------------------------------------------------------------------------
__global__ __launch_bounds__(256, 1) void wavefront_kernel(WParams prm, int gper)
{
    extern __shared__ char base[];
    const uint32_t base_u = smem_u32(base);

    const int tid   = threadIdx.x;
    const int bid   = blockIdx.x;
    const int warp  = tid >> 5;
    const int lane  = tid & 31;
    const int gsize = gridDim.x * blockDim.x;
    const int gtid  = bid * blockDim.x + tid;

    // ---- static tile schedule (133 tiles) ----
    int layer = -1, n0 = 0, k0 = 0, k1 = 0, slot = 0, src = 0;
    {
        int b = bid;
        if      (b <  96) { layer = 0; src = 1; int nt = b >> 2, kc = b & 3; n0 = nt * 128; slot = kc; k0 = kc * 256; k1 = k0 + 256; }
        else if (b < 108) { int i = b - 96; layer = 1; src = 0; int nt = i >> 2, kc = i & 3; n0 = nt * 128; slot = kc; k0 = kc * 256; k1 = k0 + 256; }
        else if (b < 111) { layer = 1; src = 1; n0 = (b - 108) * 128; slot = 4; k0 = 0; k1 = 128; }
        else if (b == 111){ layer = 2; src = 0; n0 = 0; slot = 0; k0 = 0; k1 = 128; }
        else if (b == 112){ layer = 2; src = 1; n0 = 0; slot = 1; k0 = 0; k1 = 23;  }
        else if (b < 119) { layer = 3; src = 0; n0 = (b - 113) * 128; slot = 0; k0 = 0; k1 = 151; }
        else if (b < 125) { layer = 3; src = 1; n0 = (b - 119) * 128; slot = 1; k0 = 0; k1 = 256; }
        else if (b < 128) { layer = 4; src = 0; n0 = (b - 125) * 128; slot = 0; k0 = 0; k1 = 256; }
        else if (b < 131) { layer = 4; src = 1; n0 = (b - 128) * 128; slot = 1; k0 = 0; k1 = 128; }
        else if (b == 131){ layer = 5; src = 0; n0 = 0; slot = 0; k0 = 0; k1 = 128; }
        else if (b == 132){ layer = 5; src = 1; n0 = 0; slot = 1; k0 = 0; k1 = 8;   }
    }

    const int tabU [6] = {1024, 128, 23, 256, 128, 8};
    const int tabTU[6] = {3072, 384, 69, 768, 384, 24};
    const int tabPO[6] = {0, 393216, 454656, 459072, 508224, 532800};
    const int tabHO[6] = {0, 32768, 36864, 37600, 45792, 49888};

    int threeU = 0, instride = 0, Ul = 0, klen = 0, kpad = 0;
    const float* hbase = nullptr;
    const float* inbuf = nullptr;
    float* Pb = nullptr;

    if (layer >= 0) {
        threeU = tabTU[layer];
        Ul     = tabU[layer];
        klen   = k1 - k0;
        kpad   = (klen + 15) & ~15;
        hbase  = g_h + tabHO[layer];
        switch (layer) {
            case 1: inbuf = g_seq1; instride = 1024; break;
            case 2: inbuf = g_cat;  instride = 151;  break;
            case 3: inbuf = g_cat;  instride = 151;  break;
            case 4: inbuf = g_seq4; instride = 256;  break;
            case 5: inbuf = g_seq5; instride = 128;  break;
            default: break;
        }
        Pb = g_P + tabPO[layer] + (size_t)slot * 32 * threeU;

        // ---- one-time weight conversion: sWhi/sWlo [kpad][136 bf16]
        const float* W = src ? prm.Rw[layer] : prm.Kw[layer];
        for (int i = tid; i < kpad * 128; i += 256) {
            int k = i >> 7;
            int n = i & 127;
            float f = 0.f;
            if (k < klen && n0 + n < threeU)
                f = W[(size_t)(k0 + k) * threeU + n0 + n];
            __nv_bfloat16 hi = __float2bfloat16(f);
            float lo = f - __bfloat162float(hi);
            *(unsigned short*)(base + OFF_WHI + k * WSTR + n * 2) =
                __bfloat16_as_ushort(hi);
            *(unsigned short*)(base + OFF_WLO + k * WSTR + n * 2) =
                __bfloat16_as_ushort(__float2bfloat16(lo));
        }
    }

    // zero hidden states
    for (int i = gtid; i < 50144; i += gsize) g_h[i] = 0.f;
    grid_sync(gper);

    // per-warp fragment addressing
    const int n16 = warp << 4;                       // warp's 16-col slice
    const uint32_t aAddrHi = base_u + OFF_HHI + (lane & 15) * HSTR + ((lane >> 4) << 4);
    const uint32_t aAddrLo = base_u + OFF_HLO + (lane & 15) * HSTR + ((lane >> 4) << 4);
    const uint32_t bColOff = (uint32_t)((n16 + ((lane >> 4) << 3)) * 2);
    const uint32_t bAddrHi = base_u + OFF_WHI + (lane & 15) * WSTR + bColOff;
    const uint32_t bAddrLo = base_u + OFF_WLO + (lane & 15) * WSTR + bColOff;

    for (int s = 0; s < NSTEPS; ++s) {
        // ===================== phase 1 (HMMA) =====================
        if (layer >= 0) {
            int t = s - layer;
            if ((unsigned)t < 512u) {
                // ---- stage H/input as bf16 hi/lo: sH[32][kpad]
#pragma unroll
                for (int b = 0; b < 32; b++) {
                    for (int k = tid; k < kpad; k += 256) {
                        float f = 0.f;
                        if (k < klen) {
                            const float* p = src
                                ? (hbase + b * Ul + k0 + k)
                                : (inbuf + ((size_t)(b * 512 + t)) * instride + k0 + k);
                            f = __ldcg(p);
                        }
                        __nv_bfloat16 hi = __float2bfloat16(f);
                        float lo = f - __bfloat162float(hi);
                        *(unsigned short*)(base + OFF_HHI + b * HSTR + k * 2) =
                            __bfloat16_as_ushort(hi);
                        *(unsigned short*)(base + OFF_HLO + b * HSTR + k * 2) =
                            __bfloat16_as_ushort(__float2bfloat16(lo));
                    }
                }
                __syncthreads();

                // ---- mma over k16 steps
                float acc[2][2][4];
#pragma unroll
                for (int mt = 0; mt < 2; mt++)
#pragma unroll
                    for (int j = 0; j < 2; j++)
#pragma unroll
                        for (int e = 0; e < 4; e++) acc[mt][j][e] = 0.f;

                for (int k16 = 0; k16 < kpad; k16 += 16) {
                    uint32_t ah[2][4], al[2][4], bh[4], bl[4];
                    ldsm4(ah[0], aAddrHi + k16 * 2);
                    ldsm4(ah[1], aAddrHi + k16 * 2 + 16 * HSTR);
                    ldsm4(al[0], aAddrLo + k16 * 2);
                    ldsm4(al[1], aAddrLo + k16 * 2 + 16 * HSTR);
                    ldsm4t(bh, bAddrHi + k16 * WSTR);
                    ldsm4t(bl, bAddrLo + k16 * WSTR);
#pragma unroll
                    for (int mt = 0; mt < 2; mt++) {
#pragma unroll
                        for (int j = 0; j < 2; j++) {
                            mma16816(acc[mt][j], ah[mt], bh + 2 * j);
                            mma16816(acc[mt][j], ah[mt], bl + 2 * j);
                            mma16816(acc[mt][j], al[mt], bh + 2 * j);
                        }
                    }
                }
                __syncthreads();

                // ---- store partials: P[b][threeU]
#pragma unroll
                for (int mt = 0; mt < 2; mt++) {
#pragma unroll
                    for (int j = 0; j < 2; j++) {
                        int r0 = mt * 16 + (lane >> 2);
                        int cb = n0 + n16 + j * 8 + ((lane & 3) << 1);
#pragma unroll
                        for (int half = 0; half < 2; half++) {
                            int rr = r0 + half * 8;
                            float v0 = acc[mt][j][half * 2 + 0];
                            float v1 = acc[mt][j][half * 2 + 1];
                            if (cb < threeU)     Pb[(size_t)rr * threeU + cb] = v0;
                            if (cb + 1 < threeU) Pb[(size_t)rr * threeU + cb + 1] = v1;
                        }
                    }
                }
            }
        }
        grid_sync(gper);

        // ===================== phase 2 (flattened) =====================
        for (int oid = gtid; oid < 50144; oid += gsize) {
            if (oid < 32768)
                gate_one<0, 1024, 3072, 0, 4, 0,      0,     1>(oid,         s, prm);
            else if (oid < 36864)
                gate_one<1, 128,  384,  4, 5, 393216, 32768, 1>(oid - 32768, s, prm);
            else if (oid < 37600)
                gate_one<2, 23,   69,   1, 2, 454656, 36864, 0>(oid - 36864, s, prm);
            else if (oid < 45792)
                gate_one<3, 256,  768,  1, 2, 459072, 37600, 1>(oid - 37600, s, prm);
            else if (oid < 49888)
                gate_one<4, 128,  384,  1, 2, 508224, 45792, 1>(oid - 45792, s, prm);
            else
                gate_one<5, 8,    24,   1, 2, 532800, 49888, 0>(oid - 49888, s, prm);
        }
        grid_sync(gper);
    }
}

// ---------------------------------------------------------------------------
// kernel_launch
// ---------------------------------------------------------------------------
extern "C" void kernel_launch(void* const* d_in, const int* in_sizes, int n_in,
                              void* d_out, int out_size)
{
    (void)in_sizes; (void)n_in; (void)out_size;
    const float* x = (const float*)d_in[0];

    WParams prm;
    for (int i = 0; i < 6; i++) {
        prm.Kw[i] = (const float*)d_in[1 + 3 * i];
        prm.Rw[i] = (const float*)d_in[2 + 3 * i];
        prm.Bw[i] = (const float*)d_in[3 + 3 * i];
    }
    prm.out = (float*)d_out;

    float* xp = 0;
    cudaGetSymbolAddress((void**)&xp, g_xp);

    // layer-0 input projection GEMM
    dim3 grid(3072 / 64, 16384 / 128);
    gemm_bias_kernel<<<grid, 256>>>(x, 512, prm.Kw[0], prm.Bw[0], xp, 3072, 512);

    int nb = 0;
    cudaDeviceGetAttribute(&nb, cudaDevAttrMultiProcessorCount, 0);
    if (nb <= 0) nb = 148;
    if (nb > 152) nb = 152;
    nb &= ~7;                 // multiple of 8 for the hierarchical barrier
    if (nb < 136) nb = 136;   // schedule needs >= 133 blocks

    cudaFuncSetAttribute(wavefront_kernel,
                         cudaFuncAttributeMaxDynamicSharedMemorySize, WF_SMEM);
    wavefront_kernel<<<nb, 256, WF_SMEM>>>(prm, nb >> 3);
}